// round 5
// baseline (speedup 1.0000x reference)
#include <cuda_runtime.h>

// Problem constants (fixed shapes for SNNModel_67611375174158)
#define B_DIM   128
#define T_DIM   128
#define BT      (B_DIM * T_DIM)          // 16384 rows
#define NIN     2312                     // 2*34*34
#define NCH     (NIN / 4)                // 578 int4 chunks per row
#define NFULL   (NCH / 32)               // 18 full 32-chunk groups
#define NTAIL   (NCH - NFULL * 32)       // 2 tail chunks
#define NHID    2048
#define NOUT    10
#define ALPHA_F 0.001f

#define NS_OUT  (BT * NOUT)                       // 163840 spike floats
#define TOT_OUT (NS_OUT + NHID * 16 + NOUT * 16)  // 196768 total floats
#define NB_FUSED 32
#define CHUNK   (TOT_OUT / NB_FUSED)              // 6149 exact

#define NROWBLK (BT / 8)                          // 2048 row blocks (8 warps each)

// Scratch (no allocations allowed -> __device__ globals)
__device__ unsigned char      g_accT[BT];   // [t*128+b]: acc&15 | any<<4
__device__ unsigned char      g_accB[BT];   // [b*128+t]: acc&15 | any<<4
__device__ unsigned long long g_A1pack;     // 16 x 4-bit A1 table

// ---------------------------------------------------------------------------
// Frame scan: one warp per (b,t) row. ids staged in smem (halves LDG issue
// pressure). Extra block builds the packed A1 table concurrently.
// ---------------------------------------------------------------------------
__global__ void __launch_bounds__(256) k_rowacc(const int*   __restrict__ frames,
                                                const int*   __restrict__ ids,
                                                const int*   __restrict__ nid0,
                                                const float* __restrict__ vth0,
                                                const float* __restrict__ map0) {
    __shared__ int4 sIds[NCH];
    __shared__ int  sA1[16];
    int tid = threadIdx.x;

    const int4* ids4 = reinterpret_cast<const int4*>(ids);
    for (int i = tid; i < NCH; i += 256) sIds[i] = ids4[i];
    if (tid < 16) sA1[tid] = 0;
    __syncthreads();

    if (blockIdx.x == NROWBLK) {
        // A1[p] = XOR_{j: mem_map0[j,p] >= v_th0[j]} neuron_id0[j]  (values < 16)
        int loc[16];
        #pragma unroll
        for (int p = 0; p < 16; p++) loc[p] = 0;
        for (int j = tid; j < NHID; j += 256) {
            int   nid = __ldg(&nid0[j]);
            float vt  = __ldg(&vth0[j]);
            const float4* r = reinterpret_cast<const float4*>(map0 + (size_t)j * 16);
            #pragma unroll
            for (int q = 0; q < 4; q++) {
                float4 mv = __ldg(&r[q]);
                if (mv.x >= vt) loc[q * 4 + 0] ^= nid;
                if (mv.y >= vt) loc[q * 4 + 1] ^= nid;
                if (mv.z >= vt) loc[q * 4 + 2] ^= nid;
                if (mv.w >= vt) loc[q * 4 + 3] ^= nid;
            }
        }
        #pragma unroll
        for (int p = 0; p < 16; p++)
            if (loc[p]) atomicXor(&sA1[p], loc[p]);
        __syncthreads();
        if (tid == 0) {
            unsigned long long pk = 0;
            #pragma unroll
            for (int p = 0; p < 16; p++)
                pk |= (unsigned long long)(sA1[p] & 15) << (4 * p);
            g_A1pack = pk;
        }
        return;
    }

    int wid  = (blockIdx.x * 256 + tid) >> 5;   // row = b*T + t
    int lane = tid & 31;

    const int4* row4 = reinterpret_cast<const int4*>(frames + (size_t)wid * NIN);

    unsigned x = 0, any = 0;
    #pragma unroll 6
    for (int g = 0; g < NFULL; g++) {
        int4 v  = __ldg(&row4[g * 32 + lane]);
        int4 id = sIds[g * 32 + lane];
        if (v.x) x ^= (unsigned)id.x & 15u;
        if (v.y) x ^= (unsigned)id.y & 15u;
        if (v.z) x ^= (unsigned)id.z & 15u;
        if (v.w) x ^= (unsigned)id.w & 15u;
        any |= (unsigned)(v.x | v.y | v.z | v.w);
    }
    if (lane < NTAIL) {
        int4 v  = __ldg(&row4[NFULL * 32 + lane]);
        int4 id = sIds[NFULL * 32 + lane];
        if (v.x) x ^= (unsigned)id.x & 15u;
        if (v.y) x ^= (unsigned)id.y & 15u;
        if (v.z) x ^= (unsigned)id.z & 15u;
        if (v.w) x ^= (unsigned)id.w & 15u;
        any |= (unsigned)(v.x | v.y | v.z | v.w);
    }

    unsigned acc  = __reduce_xor_sync(0xFFFFFFFFu, x);
    unsigned anyv = __reduce_or_sync(0xFFFFFFFFu, any);

    if (lane == 0) {
        int b = wid >> 7, t = wid & 127;
        unsigned char v = (unsigned char)((acc & 15u) | (anyv ? 16u : 0u));
        g_accT[t * 128 + b] = v;
        g_accB[b * 128 + t] = v;
    }
}

// ---------------------------------------------------------------------------
// Fused scan + epilogue: register-resident scan (b-major acc row in 8 LDG.128,
// A1 as packed 64-bit), branch-free, then each block writes its output slice.
// ---------------------------------------------------------------------------
__global__ void __launch_bounds__(256) k_fused(float*       __restrict__ out,
                                               const float* __restrict__ map0,
                                               const float* __restrict__ map1,
                                               const float* __restrict__ vth1) {
    __shared__ unsigned      sS1w[128 * 33];   // packed s1 bytes, padded rows
    __shared__ int           sc0[16], sc1[16];
    __shared__ unsigned      sSpk[16];
    __shared__ unsigned      sM[4];            // 128-bit active-timestep mask
    __shared__ unsigned char sDt8[T_DIM];      // dt (0 if inactive)
    __shared__ unsigned char sAm8[T_DIM];      // 0x0F if active else 0

    int tid  = threadIdx.x;
    int lane = tid & 31;

    if (tid < 16)                   { sc0[tid] = 0; sc1[tid] = 0; }
    else if (tid >= 16 && tid < 32) { sSpk[tid - 16] = 0; }
    __syncthreads();

    // Phase B: tid<128 -> has[t] from t-major global; tid>=128 -> spike LUT
    if (tid < 128) {
        const unsigned* w = reinterpret_cast<const unsigned*>(g_accT) + tid * 32;
        unsigned o = 0;
        #pragma unroll
        for (int k = 0; k < 32; k++) o |= __ldg(&w[k]);
        int has = (o & 0x10101010u) ? 1 : 0;
        unsigned bal = __ballot_sync(0xFFFFFFFFu, has);
        if (lane == 0) sM[tid >> 5] = bal;
    } else {
        for (int q = tid - 128; q < 160; q += 128) {
            int k = q >> 4, s = q & 15;
            if (__ldg(&map1[k * 16 + s]) >= __ldg(&vth1[k]))
                atomicOr(&sSpk[s], 1u << k);
        }
    }
    __syncthreads();

    // Phase C: per-t delta_t from previous active timestep (clz-based)
    if (tid < 128) {
        int t = tid;
        int word = t >> 5, bit = t & 31;
        int active = (sM[word] >> bit) & 1;
        unsigned m = bit ? (sM[word] & ((1u << bit) - 1u)) : 0u;
        int tl = 0;
        int w = word;
        while (true) {
            if (m) { tl = (w << 5) + 31 - __clz(m); break; }
            if (--w < 0) break;
            m = sM[w];
        }
        sDt8[t] = (unsigned char)(active ? ((t - tl) & 15) : 0);
        sAm8[t] = (unsigned char)(active ? 0x0F : 0x00);
    }
    __syncthreads();

    // Phase D: register-resident per-batch scan (thread b < 128)
    if (tid < 128) {
        int b = tid;
        unsigned aw[32];
        {
            const uint4* rb = reinterpret_cast<const uint4*>(g_accB) + b * 8;
            #pragma unroll
            for (int r = 0; r < 8; r++) {
                uint4 v = __ldg(&rb[r]);
                aw[r * 4 + 0] = v.x; aw[r * 4 + 1] = v.y;
                aw[r * 4 + 2] = v.z; aw[r * 4 + 3] = v.w;
            }
        }
        unsigned long long A1p = g_A1pack;
        const unsigned* dtW = reinterpret_cast<const unsigned*>(sDt8);
        const unsigned* amW = reinterpret_cast<const unsigned*>(sAm8);

        unsigned s0 = 0, s1 = 0;
        unsigned long long h0lo = 0, h0hi = 0, h1lo = 0, h1hi = 0;

        #pragma unroll 4
        for (int w = 0; w < 32; w++) {
            unsigned am = amW[w];
            unsigned dt = dtW[w];
            unsigned x  = (aw[w] & am) ^ dt;     // per-byte (dt ^ a), gated
            unsigned pk = 0;
            #pragma unroll
            for (int j = 0; j < 4; j++) {
                unsigned amb = (am >> (8 * j));          // low nibble 0xF or 0
                unsigned xb  = (x  >> (8 * j)) & 15u;
                s0 ^= xb;
                unsigned long long act64 = (unsigned long long)(amb & 1u);
                unsigned long long inc0  = act64 << ((s0 & 7u) << 3);
                h0lo += (s0 < 8u) ? inc0 : 0ULL;
                h0hi += (s0 < 8u) ? 0ULL : inc0;
                unsigned a1 = (unsigned)(A1p >> (s0 << 2)) & amb & 15u;
                unsigned db = (dt >> (8 * j)) & 15u;
                s1 ^= db ^ a1;
                unsigned long long inc1 = act64 << ((s1 & 7u) << 3);
                h1lo += (s1 < 8u) ? inc1 : 0ULL;
                h1hi += (s1 < 8u) ? 0ULL : inc1;
                unsigned sb = s1 | (((amb & 1u) - 1u) & 0xFFu);  // 0xFF if inactive
                pk |= sb << (8 * j);
            }
            sS1w[b * 33 + w] = pk;
        }

        // Histogram finalize: expand byte bins to 16-bit lanes, warp-reduce.
        const unsigned long long EM = 0x00FF00FF00FF00FFULL;
        unsigned long long e0 = h0lo & EM, e1 = (h0lo >> 8) & EM;
        unsigned long long e2 = h0hi & EM, e3 = (h0hi >> 8) & EM;
        unsigned long long f0 = h1lo & EM, f1 = (h1lo >> 8) & EM;
        unsigned long long f2 = h1hi & EM, f3 = (h1hi >> 8) & EM;
        #pragma unroll
        for (int o = 16; o; o >>= 1) {
            e0 += __shfl_xor_sync(0xFFFFFFFFu, e0, o);
            e1 += __shfl_xor_sync(0xFFFFFFFFu, e1, o);
            e2 += __shfl_xor_sync(0xFFFFFFFFu, e2, o);
            e3 += __shfl_xor_sync(0xFFFFFFFFu, e3, o);
            f0 += __shfl_xor_sync(0xFFFFFFFFu, f0, o);
            f1 += __shfl_xor_sync(0xFFFFFFFFu, f1, o);
            f2 += __shfl_xor_sync(0xFFFFFFFFu, f2, o);
            f3 += __shfl_xor_sync(0xFFFFFFFFu, f3, o);
        }
        if (lane < 16) {
            int slot = (lane & 7) >> 1;
            unsigned long long c0 = (lane & 1) ? ((lane >= 8) ? e3 : e1)
                                               : ((lane >= 8) ? e2 : e0);
            unsigned long long c1 = (lane & 1) ? ((lane >= 8) ? f3 : f1)
                                               : ((lane >= 8) ? f2 : f0);
            atomicAdd(&sc0[lane], (int)((c0 >> (slot * 16)) & 0xFFFFu));
            atomicAdd(&sc1[lane], (int)((c1 >> (slot * 16)) & 0xFFFFu));
        }
    }
    __syncthreads();

    // Phase F: write this block's slice of the output
    int start = blockIdx.x * CHUNK;
    int end   = start + CHUNK;
    for (int e = start + tid; e < end; e += 256) {
        float r;
        if (e < NS_OUT) {
            int bt = e / NOUT;
            int k  = e - bt * NOUT;
            int b  = bt >> 7, t = bt & 127;
            unsigned s = (sS1w[b * 33 + (t >> 2)] >> ((t & 3) * 8)) & 0xFFu;
            unsigned msk = sSpk[s & 15];
            r = (s != 0xFFu && ((msk >> k) & 1u)) ? 1.0f : 0.0f;
        } else if (e < NS_OUT + NHID * 16) {
            int f = e - NS_OUT;
            int p = f & 15;
            r = ALPHA_F * (float)sc0[p] * ((float)p - __ldg(&map0[f]));
        } else {
            int f = e - NS_OUT - NHID * 16;
            int p = f & 15;
            r = ALPHA_F * (float)sc1[p] * ((float)p - __ldg(&map1[f]));
        }
        out[e] = r;
    }
}

// ---------------------------------------------------------------------------
// Inputs (metadata order): frames, input_neuron_id, tau0, v_th0, neuron_id0,
// mem_map0, syn_w0, tau1, v_th1, neuron_id1, mem_map1, syn_w1
// ---------------------------------------------------------------------------
extern "C" void kernel_launch(void* const* d_in, const int* in_sizes, int n_in,
                              void* d_out, int out_size) {
    const int*   frames = (const int*)  d_in[0];
    const int*   inid   = (const int*)  d_in[1];
    const float* vth0   = (const float*)d_in[3];
    const int*   nid0   = (const int*)  d_in[4];
    const float* map0   = (const float*)d_in[5];
    const float* vth1   = (const float*)d_in[8];
    const float* map1   = (const float*)d_in[10];

    k_rowacc<<<NROWBLK + 1, 256>>>(frames, inid, nid0, vth0, map0);
    k_fused<<<NB_FUSED, 256>>>((float*)d_out, map0, map1, vth1);
}